// round 2
// baseline (speedup 1.0000x reference)
#include <cuda_runtime.h>
#include <cuda_bf16.h>

#define BATCH 8
#define CIN   256
#define DQK   32
#define NPIX  4096   // 64*64

// Scratch (static device memory: allocation-free rule)
__device__ float g_q[(size_t)BATCH * NPIX * DQK];   // [b][i][d]   4 MB
__device__ float g_v[(size_t)BATCH * NPIX * CIN];   // [b][j][c]  33.5 MB
__device__ float g_m[(size_t)BATCH * NPIX];         // row max of energy

// ---------------------------------------------------------------------------
// Kernel 1: fused projection.  Out[j][o] = sum_c x[b][c][j] * W[o][c] + bias
// W rows 0..31 = q_w, rows 32..287 = v_w.  64x64 tile, k-chunks of 32.
// ---------------------------------------------------------------------------
__global__ __launch_bounds__(256) void proj_kernel(
    const float* __restrict__ x,
    const float* __restrict__ qw, const float* __restrict__ qb,
    const float* __restrict__ vw, const float* __restrict__ vb)
{
    int b  = blockIdx.z;
    int j0 = blockIdx.x * 64;
    int o0 = blockIdx.y * 64;

    __shared__ float Xs[32][64];
    __shared__ float Ws[32][65];   // Ws[kk][oo]

    int tid = threadIdx.x;
    int tx = tid & 15;      // -> output dim (4 outputs)
    int ty = tid >> 4;      // -> pixel dim  (4 pixels)

    float acc[4][4] = {};
    const float* xb = x + (size_t)b * CIN * NPIX;

    for (int c0 = 0; c0 < CIN; c0 += 32) {
        #pragma unroll
        for (int r = 0; r < 8; r++) {
            int idx = tid + r * 256;
            int kk = idx >> 6, jj = idx & 63;
            Xs[kk][jj] = xb[(size_t)(c0 + kk) * NPIX + j0 + jj];
        }
        #pragma unroll
        for (int r = 0; r < 8; r++) {
            int idx = tid + r * 256;
            int oo = idx >> 5, kk = idx & 31;
            int o = o0 + oo;
            float w = 0.f;
            if (o < DQK)          w = qw[o * CIN + c0 + kk];
            else if (o < DQK+CIN) w = vw[(o - DQK) * CIN + c0 + kk];
            Ws[kk][oo] = w;
        }
        __syncthreads();
        #pragma unroll
        for (int kk = 0; kk < 32; kk++) {
            float a[4], w[4];
            #pragma unroll
            for (int i = 0; i < 4; i++) a[i] = Xs[kk][ty * 4 + i];
            #pragma unroll
            for (int i = 0; i < 4; i++) w[i] = Ws[kk][tx * 4 + i];
            #pragma unroll
            for (int i = 0; i < 4; i++)
                #pragma unroll
                for (int o = 0; o < 4; o++)
                    acc[i][o] += a[i] * w[o];
        }
        __syncthreads();
    }

    #pragma unroll
    for (int i = 0; i < 4; i++) {
        int j = j0 + ty * 4 + i;
        #pragma unroll
        for (int oi = 0; oi < 4; oi++) {
            int o = o0 + tx * 4 + oi;
            if (o < DQK)
                g_q[((size_t)b * NPIX + j) * DQK + o] = acc[i][oi] + qb[o];
            else if (o < DQK + CIN)
                g_v[((size_t)b * NPIX + j) * CIN + (o - DQK)] = acc[i][oi] + vb[o - DQK];
        }
    }
}

// ---------------------------------------------------------------------------
// Kernel 2: per-row max of energy.  128 threads, 1 query each, q in registers,
// K tiles broadcast from smem.
// ---------------------------------------------------------------------------
__global__ __launch_bounds__(128) void rowmax_kernel()
{
    int b = blockIdx.y;
    int i = blockIdx.x * 128 + threadIdx.x;

    __shared__ float Ks[64][32];

    float q[DQK];
    const float* qrow = g_q + ((size_t)b * NPIX + i) * DQK;
    #pragma unroll
    for (int d = 0; d < DQK; d++) q[d] = qrow[d];

    float m = -1e30f;
    for (int j0 = 0; j0 < NPIX; j0 += 64) {
        const float* ksrc = g_q + ((size_t)b * NPIX + j0) * DQK;
        #pragma unroll
        for (int r = 0; r < 16; r++) {
            int idx = threadIdx.x + r * 128;
            Ks[idx >> 5][idx & 31] = ksrc[idx];
        }
        __syncthreads();
        #pragma unroll 4
        for (int j = 0; j < 64; j++) {
            float s0 = 0, s1 = 0, s2 = 0, s3 = 0;
            #pragma unroll
            for (int d = 0; d < DQK; d += 4) {
                s0 += q[d + 0] * Ks[j][d + 0];
                s1 += q[d + 1] * Ks[j][d + 1];
                s2 += q[d + 2] * Ks[j][d + 2];
                s3 += q[d + 3] * Ks[j][d + 3];
            }
            m = fmaxf(m, (s0 + s1) + (s2 + s3));
        }
        __syncthreads();
    }
    g_m[(size_t)b * NPIX + i] = m;
}

// ---------------------------------------------------------------------------
// Kernel 3: attention.  CTA = 32 queries, loop over 32-key tiles.
// S recomputed (m known), P = exp(S - m) into smem, O += P*V with 4q x 8c
// register tiles.  Epilogue: normalize, smem transpose, fused gamma*out + x.
// ---------------------------------------------------------------------------
__global__ __launch_bounds__(256) void attn_kernel(
    const float* __restrict__ x,
    const float* __restrict__ gamma,
    float* __restrict__ out)
{
    int b  = blockIdx.y;
    int i0 = blockIdx.x * 32;

    __shared__ __align__(16) float Qs[32][33];
    __shared__ __align__(16) float Ks[32][33];
    __shared__ __align__(16) float Ps[32][33];    // Ps[key][query]
    __shared__ __align__(16) float Vs[32][260];   // also reused as O transpose buffer
    __shared__ float lred[32][17];
    __shared__ float lbuf[32];

    int tid = threadIdx.x;

    // load Q tile
    #pragma unroll
    for (int r = 0; r < 4; r++) {
        int idx = tid + r * 256;
        Qs[idx >> 5][idx & 31] = g_q[((size_t)b * NPIX + i0) * DQK + idx];
    }

    // S-compute mapping: 16x16 threads, 2x2 micro tile
    int sx = tid & 15;   // key pair 2sx, 2sx+1
    int sy = tid >> 4;   // query pair 2sy, 2sy+1
    float m0 = g_m[(size_t)b * NPIX + i0 + 2 * sy];
    float m1 = g_m[(size_t)b * NPIX + i0 + 2 * sy + 1];
    float l0 = 0.f, l1 = 0.f;

    // PV mapping: queries {ty+8k}, channels {tx+32k}
    int tx = tid & 31;
    int ty = tid >> 5;
    float acc[4][8] = {};

    for (int j0 = 0; j0 < NPIX; j0 += 32) {
        // load K tile
        const float* ksrc = g_q + ((size_t)b * NPIX + j0) * DQK;
        #pragma unroll
        for (int r = 0; r < 4; r++) {
            int idx = tid + r * 256;
            Ks[idx >> 5][idx & 31] = ksrc[idx];
        }
        // load V tile (float4)
        const float4* vsrc = (const float4*)(g_v + ((size_t)b * NPIX + j0) * CIN);
        #pragma unroll
        for (int r = 0; r < 8; r++) {
            int idx = tid + r * 256;           // float4 index, 0..2047
            int j = idx >> 6, c4 = idx & 63;
            float4 v = vsrc[idx];
            *(float4*)&Vs[j][c4 * 4] = v;
        }
        __syncthreads();

        // S + exp
        float s00 = 0, s01 = 0, s10 = 0, s11 = 0;
        #pragma unroll
        for (int d = 0; d < DQK; d++) {
            float a0 = Qs[2 * sy][d],  a1 = Qs[2 * sy + 1][d];
            float b0 = Ks[2 * sx][d],  b1 = Ks[2 * sx + 1][d];
            s00 += a0 * b0; s01 += a0 * b1;
            s10 += a1 * b0; s11 += a1 * b1;
        }
        float p00 = __expf(s00 - m0), p01 = __expf(s01 - m0);
        float p10 = __expf(s10 - m1), p11 = __expf(s11 - m1);
        l0 += p00 + p01;
        l1 += p10 + p11;
        Ps[2 * sx][2 * sy]     = p00;  Ps[2 * sx + 1][2 * sy]     = p01;
        Ps[2 * sx][2 * sy + 1] = p10;  Ps[2 * sx + 1][2 * sy + 1] = p11;
        __syncthreads();

        // O += P * V
        #pragma unroll 4
        for (int j = 0; j < 32; j++) {
            float p[4];
            #pragma unroll
            for (int qi = 0; qi < 4; qi++) p[qi] = Ps[j][ty + 8 * qi];  // broadcast
            #pragma unroll
            for (int k = 0; k < 8; k++) {
                float v = Vs[j][tx + 32 * k];                           // conflict-free
                #pragma unroll
                for (int qi = 0; qi < 4; qi++) acc[qi][k] += p[qi] * v;
            }
        }
        __syncthreads();
    }

    // reduce l across the 16 key-columns per query
    lred[2 * sy][sx]     = l0;
    lred[2 * sy + 1][sx] = l1;
    __syncthreads();
    if (tid < 32) {
        float l = 0.f;
        #pragma unroll
        for (int k = 0; k < 16; k++) l += lred[tid][k];
        lbuf[tid] = 1.0f / l;
    }
    __syncthreads();

    // normalized O into Vs (reuse), then transpose-store fused with gamma*out + x
    #pragma unroll
    for (int qi = 0; qi < 4; qi++) {
        float inv = lbuf[ty + 8 * qi];
        #pragma unroll
        for (int k = 0; k < 8; k++)
            Vs[ty + 8 * qi][tx + 32 * k] = acc[qi][k] * inv;
    }
    __syncthreads();

    float g = gamma[0];
    int w = ty;        // warp id 0..7 -> channel stride
    int lane = tx;     // -> query (fast output axis)
    for (int c = w; c < CIN; c += 8) {
        float val = Vs[lane][c];
        size_t oidx = ((size_t)b * CIN + c) * NPIX + i0 + lane;
        out[oidx] = g * val + x[oidx];
    }
}

// ---------------------------------------------------------------------------
extern "C" void kernel_launch(void* const* d_in, const int* in_sizes, int n_in,
                              void* d_out, int out_size)
{
    const float* x     = (const float*)d_in[0];
    const float* q_w   = (const float*)d_in[1];
    const float* q_b   = (const float*)d_in[2];
    const float* v_w   = (const float*)d_in[3];
    const float* v_b   = (const float*)d_in[4];
    const float* gamma = (const float*)d_in[5];
    float* out = (float*)d_out;

    proj_kernel<<<dim3(NPIX / 64, 5, BATCH), 256>>>(x, q_w, q_b, v_w, v_b);
    rowmax_kernel<<<dim3(NPIX / 128, BATCH), 128>>>();
    attn_kernel<<<dim3(NPIX / 32, BATCH), 256>>>(x, gamma, out);
}

// round 3
// speedup vs baseline: 1.0031x; 1.0031x over previous
#include <cuda_runtime.h>
#include <cuda_bf16.h>

#define BATCH 8
#define CIN   256
#define DQK   32
#define NPIX  4096   // 64*64

// Scratch (static device memory: allocation-free rule)
__device__ float g_q[(size_t)BATCH * NPIX * DQK];   // [b][i][d]   4 MB
__device__ float g_v[(size_t)BATCH * NPIX * CIN];   // [b][j][c]  33.5 MB
__device__ float g_m[(size_t)BATCH * NPIX];         // row max of energy

// ---------------------------------------------------------------------------
// Kernel 1: fused projection.  Out[j][o] = sum_c x[b][c][j] * W[o][c] + bias
// W rows 0..31 = q_w, rows 32..287 = v_w.  64x64 tile, k-chunks of 32.
// ---------------------------------------------------------------------------
__global__ __launch_bounds__(256) void proj_kernel(
    const float* __restrict__ x,
    const float* __restrict__ qw, const float* __restrict__ qb,
    const float* __restrict__ vw, const float* __restrict__ vb)
{
    int b  = blockIdx.z;
    int j0 = blockIdx.x * 64;
    int o0 = blockIdx.y * 64;

    __shared__ float Xs[32][64];
    __shared__ float Ws[32][65];   // Ws[kk][oo]

    int tid = threadIdx.x;
    int tx = tid & 15;      // -> output dim (4 outputs)
    int ty = tid >> 4;      // -> pixel dim  (4 pixels)

    float acc[4][4] = {};
    const float* xb = x + (size_t)b * CIN * NPIX;

    for (int c0 = 0; c0 < CIN; c0 += 32) {
        #pragma unroll
        for (int r = 0; r < 8; r++) {
            int idx = tid + r * 256;
            int kk = idx >> 6, jj = idx & 63;
            Xs[kk][jj] = xb[(size_t)(c0 + kk) * NPIX + j0 + jj];
        }
        #pragma unroll
        for (int r = 0; r < 8; r++) {
            int idx = tid + r * 256;
            int oo = idx >> 5, kk = idx & 31;
            int o = o0 + oo;
            float w = 0.f;
            if (o < DQK)          w = qw[o * CIN + c0 + kk];
            else if (o < DQK+CIN) w = vw[(o - DQK) * CIN + c0 + kk];
            Ws[kk][oo] = w;
        }
        __syncthreads();
        #pragma unroll
        for (int kk = 0; kk < 32; kk++) {
            float a[4], w[4];
            #pragma unroll
            for (int i = 0; i < 4; i++) a[i] = Xs[kk][ty * 4 + i];
            #pragma unroll
            for (int i = 0; i < 4; i++) w[i] = Ws[kk][tx * 4 + i];
            #pragma unroll
            for (int i = 0; i < 4; i++)
                #pragma unroll
                for (int o = 0; o < 4; o++)
                    acc[i][o] += a[i] * w[o];
        }
        __syncthreads();
    }

    #pragma unroll
    for (int i = 0; i < 4; i++) {
        int j = j0 + ty * 4 + i;
        #pragma unroll
        for (int oi = 0; oi < 4; oi++) {
            int o = o0 + tx * 4 + oi;
            if (o < DQK)
                g_q[((size_t)b * NPIX + j) * DQK + o] = acc[i][oi] + qb[o];
            else if (o < DQK + CIN)
                g_v[((size_t)b * NPIX + j) * CIN + (o - DQK)] = acc[i][oi] + vb[o - DQK];
        }
    }
}

// ---------------------------------------------------------------------------
// Kernel 2: per-row max of energy.  128 threads, 1 query each, q in registers,
// K tiles broadcast from smem.
// ---------------------------------------------------------------------------
__global__ __launch_bounds__(128) void rowmax_kernel()
{
    int b = blockIdx.y;
    int i = blockIdx.x * 128 + threadIdx.x;

    __shared__ float Ks[64][32];

    float q[DQK];
    const float* qrow = g_q + ((size_t)b * NPIX + i) * DQK;
    #pragma unroll
    for (int d = 0; d < DQK; d++) q[d] = qrow[d];

    float m = -1e30f;
    for (int j0 = 0; j0 < NPIX; j0 += 64) {
        const float* ksrc = g_q + ((size_t)b * NPIX + j0) * DQK;
        #pragma unroll
        for (int r = 0; r < 16; r++) {
            int idx = threadIdx.x + r * 128;
            Ks[idx >> 5][idx & 31] = ksrc[idx];
        }
        __syncthreads();
        #pragma unroll 4
        for (int j = 0; j < 64; j++) {
            float s0 = 0, s1 = 0, s2 = 0, s3 = 0;
            #pragma unroll
            for (int d = 0; d < DQK; d += 4) {
                s0 += q[d + 0] * Ks[j][d + 0];
                s1 += q[d + 1] * Ks[j][d + 1];
                s2 += q[d + 2] * Ks[j][d + 2];
                s3 += q[d + 3] * Ks[j][d + 3];
            }
            m = fmaxf(m, (s0 + s1) + (s2 + s3));
        }
        __syncthreads();
    }
    g_m[(size_t)b * NPIX + i] = m;
}

// ---------------------------------------------------------------------------
// Kernel 3: attention.  CTA = 32 queries, loop over 32-key tiles.
// S recomputed (m known), P = exp(S - m) into smem, O += P*V with 4q x 8c
// register tiles.  Epilogue: normalize, smem transpose, fused gamma*out + x.
// ---------------------------------------------------------------------------
__global__ __launch_bounds__(256) void attn_kernel(
    const float* __restrict__ x,
    const float* __restrict__ gamma,
    float* __restrict__ out)
{
    int b  = blockIdx.y;
    int i0 = blockIdx.x * 32;

    __shared__ __align__(16) float Qs[32][33];
    __shared__ __align__(16) float Ks[32][33];
    __shared__ __align__(16) float Ps[32][33];    // Ps[key][query]
    __shared__ __align__(16) float Vs[32][260];   // also reused as O transpose buffer
    __shared__ float lred[32][17];
    __shared__ float lbuf[32];

    int tid = threadIdx.x;

    // load Q tile
    #pragma unroll
    for (int r = 0; r < 4; r++) {
        int idx = tid + r * 256;
        Qs[idx >> 5][idx & 31] = g_q[((size_t)b * NPIX + i0) * DQK + idx];
    }

    // S-compute mapping: 16x16 threads, 2x2 micro tile
    int sx = tid & 15;   // key pair 2sx, 2sx+1
    int sy = tid >> 4;   // query pair 2sy, 2sy+1
    float m0 = g_m[(size_t)b * NPIX + i0 + 2 * sy];
    float m1 = g_m[(size_t)b * NPIX + i0 + 2 * sy + 1];
    float l0 = 0.f, l1 = 0.f;

    // PV mapping: queries {ty+8k}, channels {tx+32k}
    int tx = tid & 31;
    int ty = tid >> 5;
    float acc[4][8] = {};

    for (int j0 = 0; j0 < NPIX; j0 += 32) {
        // load K tile
        const float* ksrc = g_q + ((size_t)b * NPIX + j0) * DQK;
        #pragma unroll
        for (int r = 0; r < 4; r++) {
            int idx = tid + r * 256;
            Ks[idx >> 5][idx & 31] = ksrc[idx];
        }
        // load V tile (float4)
        const float4* vsrc = (const float4*)(g_v + ((size_t)b * NPIX + j0) * CIN);
        #pragma unroll
        for (int r = 0; r < 8; r++) {
            int idx = tid + r * 256;           // float4 index, 0..2047
            int j = idx >> 6, c4 = idx & 63;
            float4 v = vsrc[idx];
            *(float4*)&Vs[j][c4 * 4] = v;
        }
        __syncthreads();

        // S + exp
        float s00 = 0, s01 = 0, s10 = 0, s11 = 0;
        #pragma unroll
        for (int d = 0; d < DQK; d++) {
            float a0 = Qs[2 * sy][d],  a1 = Qs[2 * sy + 1][d];
            float b0 = Ks[2 * sx][d],  b1 = Ks[2 * sx + 1][d];
            s00 += a0 * b0; s01 += a0 * b1;
            s10 += a1 * b0; s11 += a1 * b1;
        }
        float p00 = __expf(s00 - m0), p01 = __expf(s01 - m0);
        float p10 = __expf(s10 - m1), p11 = __expf(s11 - m1);
        l0 += p00 + p01;
        l1 += p10 + p11;
        Ps[2 * sx][2 * sy]     = p00;  Ps[2 * sx + 1][2 * sy]     = p01;
        Ps[2 * sx][2 * sy + 1] = p10;  Ps[2 * sx + 1][2 * sy + 1] = p11;
        __syncthreads();

        // O += P * V
        #pragma unroll 4
        for (int j = 0; j < 32; j++) {
            float p[4];
            #pragma unroll
            for (int qi = 0; qi < 4; qi++) p[qi] = Ps[j][ty + 8 * qi];  // broadcast
            #pragma unroll
            for (int k = 0; k < 8; k++) {
                float v = Vs[j][tx + 32 * k];                           // conflict-free
                #pragma unroll
                for (int qi = 0; qi < 4; qi++) acc[qi][k] += p[qi] * v;
            }
        }
        __syncthreads();
    }

    // reduce l across the 16 key-columns per query
    lred[2 * sy][sx]     = l0;
    lred[2 * sy + 1][sx] = l1;
    __syncthreads();
    if (tid < 32) {
        float l = 0.f;
        #pragma unroll
        for (int k = 0; k < 16; k++) l += lred[tid][k];
        lbuf[tid] = 1.0f / l;
    }
    __syncthreads();

    // normalized O into Vs (reuse), then transpose-store fused with gamma*out + x
    #pragma unroll
    for (int qi = 0; qi < 4; qi++) {
        float inv = lbuf[ty + 8 * qi];
        #pragma unroll
        for (int k = 0; k < 8; k++)
            Vs[ty + 8 * qi][tx + 32 * k] = acc[qi][k] * inv;
    }
    __syncthreads();

    float g = gamma[0];
    int w = ty;        // warp id 0..7 -> channel stride
    int lane = tx;     // -> query (fast output axis)
    for (int c = w; c < CIN; c += 8) {
        float val = Vs[lane][c];
        size_t oidx = ((size_t)b * CIN + c) * NPIX + i0 + lane;
        out[oidx] = g * val + x[oidx];
    }
}

// ---------------------------------------------------------------------------
extern "C" void kernel_launch(void* const* d_in, const int* in_sizes, int n_in,
                              void* d_out, int out_size)
{
    const float* x     = (const float*)d_in[0];
    const float* q_w   = (const float*)d_in[1];
    const float* q_b   = (const float*)d_in[2];
    const float* v_w   = (const float*)d_in[3];
    const float* v_b   = (const float*)d_in[4];
    const float* gamma = (const float*)d_in[5];
    float* out = (float*)d_out;

    proj_kernel<<<dim3(NPIX / 64, 5, BATCH), 256>>>(x, q_w, q_b, v_w, v_b);
    rowmax_kernel<<<dim3(NPIX / 128, BATCH), 128>>>();
    attn_kernel<<<dim3(NPIX / 32, BATCH), 256>>>(x, gamma, out);
}